// round 9
// baseline (speedup 1.0000x reference)
#include <cuda_runtime.h>
#include <math.h>

#define VN 50000
#define EN 300
#define HN 2048
#define LN 512
#define EH 2348   // E + H
#define H3 6144   // 3*H
#define NROWS_AG (LN + H3)       // 6656
#define NCHUNK 32                // L-chunks for attnapply
#define LPC 16                   // L rows per chunk
#define LOGITS_ROWS 16
#define NLB (VN / LOGITS_ROWS)   // 3125 logits blocks

// ---- scratch (device globals; no allocation allowed) ----
__device__ float g_attn_logits[LN];
__device__ float g_gh[H3];
__device__ float g_gi[H3];
__device__ float g_attn_part[NCHUNK * HN];
__device__ float g_attn_applied[HN];
__device__ float g_x[HN];
__device__ float g_hnew[HN];
__device__ float g_vlogits[VN];
__device__ unsigned g_maxbits;
__device__ float g_bmax[NLB];
__device__ float g_bsum[NLB];

__device__ __forceinline__ float warpSum(float v) {
#pragma unroll
    for (int o = 16; o; o >>= 1) v += __shfl_xor_sync(0xffffffffu, v, o);
    return v;
}

// order-preserving float<->uint encoding for deterministic atomicMax
__device__ __forceinline__ unsigned fenc(float f) {
    unsigned b = __float_as_uint(f);
    return (b & 0x80000000u) ? ~b : (b | 0x80000000u);
}
__device__ __forceinline__ float fdec(unsigned u) {
    unsigned b = (u & 0x80000000u) ? (u ^ 0x80000000u) : ~u;
    return __uint_as_float(b);
}

// Attention logits (512 rows over E+H) and gh = W_hh @ h0 + b_hh (6144 rows).
// Warp-per-row, 8 rows per 256-thread block -> 832 blocks (multi-wave).
__global__ void __launch_bounds__(256) k_attnlogits_gh(
        const int* tok_p, const float* hid, const float* emb,
        const float* attn_W, const float* attn_b,
        const float* W_hh, const float* b_hh) {
    __shared__ float4 h4s[HN / 4];        // h0 staged
    __shared__ float esh[EN + 4];         // emb row (only attn blocks use it)
    int t = threadIdx.x;
    if (blockIdx.x == 0 && t == 0) g_maxbits = 0u;
    h4s[t] = ((const float4*)hid)[t];
    h4s[t + 256] = ((const float4*)hid)[t + 256];
    if (blockIdx.x < LN / 8) {
        const float* e = emb + (long)(*tok_p) * EN;
        for (int i = t; i < EN; i += 256) esh[i] = e[i];   // FIX: cover all 300
    }
    __syncthreads();
    int lane = t & 31, warp = t >> 5;
    int row = blockIdx.x * 8 + warp;
    float s = 0.f;
    if (row < LN) {
        const float* r = attn_W + (long)row * EH;
        for (int i = lane; i < EN; i += 32) s += r[i] * esh[i];
        const float4* r4 = (const float4*)(r + EN);
#pragma unroll
        for (int k = 0; k < 16; k++) {
            float4 a = r4[lane + 32 * k];
            float4 c = h4s[lane + 32 * k];
            s += a.x * c.x + a.y * c.y + a.z * c.z + a.w * c.w;
        }
        s = warpSum(s);
        if (lane == 0) g_attn_logits[row] = s + attn_b[row];
    } else {
        int r = row - LN;
        const float4* r4 = (const float4*)(W_hh + (long)r * HN);
#pragma unroll
        for (int k = 0; k < 16; k++) {
            float4 a = r4[lane + 32 * k];
            float4 c = h4s[lane + 32 * k];
            s += a.x * c.x + a.y * c.y + a.z * c.z + a.w * c.w;
        }
        s = warpSum(s);
        if (lane == 0) g_gh[r] = s + b_hh[r];
    }
}

// Fused softmax + attn_applied partials. Every block recomputes the 512-wide
// softmax (cheap, identical across blocks), then applies its L-chunk to a
// 1024-float h-slice via float4 loads. grid = 64 blocks, 256 threads.
__global__ void k_attnapply(const float* enc, float* out) {
    __shared__ float esh[LN];
    __shared__ float red[256];
    int t = threadIdx.x;
    float v0 = g_attn_logits[t], v1 = g_attn_logits[t + 256];
    red[t] = fmaxf(v0, v1);
    __syncthreads();
    for (int s = 128; s; s >>= 1) {
        if (t < s) red[t] = fmaxf(red[t], red[t + s]);
        __syncthreads();
    }
    float m = red[0];
    __syncthreads();
    float e0 = expf(v0 - m), e1 = expf(v1 - m);
    esh[t] = e0; esh[t + 256] = e1;
    red[t] = e0 + e1;
    __syncthreads();
    for (int s = 128; s; s >>= 1) {
        if (t < s) red[t] += red[t + s];
        __syncthreads();
    }
    float inv = 1.f / red[0];

    if (blockIdx.x == 0) {  // attn_weights output
        out[VN + HN + t]       = esh[t] * inv;
        out[VN + HN + t + 256] = esh[t + 256] * inv;
    }

    int chunk = blockIdx.x >> 1, half = blockIdx.x & 1;
    int h4 = half * 256 + t;
    const float4* base = (const float4*)enc + (long)chunk * LPC * (HN / 4) + h4;
    float4 acc = make_float4(0.f, 0.f, 0.f, 0.f);
#pragma unroll
    for (int l = 0; l < LPC; l++) {
        float w = esh[chunk * LPC + l] * inv;
        float4 a = base[(long)l * (HN / 4)];
        acc.x += w * a.x; acc.y += w * a.y; acc.z += w * a.z; acc.w += w * a.w;
    }
    ((float4*)g_attn_part)[chunk * (HN / 4) + h4] = acc;
}

__global__ void k_attnapply_sum() {
    int h = blockIdx.x * 256 + threadIdx.x;
    float s = 0.f;
#pragma unroll
    for (int c = 0; c < NCHUNK; c++) s += g_attn_part[c * HN + h];
    g_attn_applied[h] = s;
}

// x = relu(comb_W @ [embedded, attn_applied] + comb_b)
// Warp-per-row, 8 rows per 256-thread block -> 256 blocks.
__global__ void __launch_bounds__(256) k_combine(const int* tok_p, const float* emb,
                                                 const float* comb_W, const float* comb_b) {
    __shared__ float4 a4s[HN / 4];
    __shared__ float esh[EN + 4];
    int t = threadIdx.x;
    a4s[t] = ((const float4*)g_attn_applied)[t];
    a4s[t + 256] = ((const float4*)g_attn_applied)[t + 256];
    {
        const float* e = emb + (long)(*tok_p) * EN;
        for (int i = t; i < EN; i += 256) esh[i] = e[i];   // FIX: cover all 300
    }
    __syncthreads();
    int lane = t & 31, warp = t >> 5;
    int row = blockIdx.x * 8 + warp;
    const float* r = comb_W + (long)row * EH;
    float s = 0.f;
    for (int i = lane; i < EN; i += 32) s += r[i] * esh[i];
    const float4* r4 = (const float4*)(r + EN);
#pragma unroll
    for (int k = 0; k < 16; k++) {
        float4 a = r4[lane + 32 * k];
        float4 c = a4s[lane + 32 * k];
        s += a.x * c.x + a.y * c.y + a.z * c.z + a.w * c.w;
    }
    s = warpSum(s);
    if (lane == 0) g_x[row] = fmaxf(s + comb_b[row], 0.f);
}

// gi = W_ih @ x + b_ih : plain 6144-row GEMV, warp-per-row, 768 blocks.
__global__ void __launch_bounds__(256) k_gru_mm(const float* W_ih, const float* b_ih) {
    __shared__ float4 x4s[HN / 4];
    int t = threadIdx.x;
    x4s[t] = ((const float4*)g_x)[t];
    x4s[t + 256] = ((const float4*)g_x)[t + 256];
    __syncthreads();
    int lane = t & 31, warp = t >> 5;
    int row = blockIdx.x * 8 + warp;
    const float4* r4 = (const float4*)(W_ih + (long)row * HN);
    float s = 0.f;
#pragma unroll
    for (int k = 0; k < 16; k++) {
        float4 a = r4[lane + 32 * k];
        float4 c = x4s[lane + 32 * k];
        s += a.x * c.x + a.y * c.y + a.z * c.z + a.w * c.w;
    }
    s = warpSum(s);
    if (lane == 0) g_gi[row] = s + b_ih[row];
}

// elementwise GRU gates -> h_new (8 blocks x 256)
__global__ void k_gru_gate(const float* hid, float* out) {
    int h = blockIdx.x * 256 + threadIdx.x;
    float ir = g_gi[h], iz = g_gi[h + HN], inn = g_gi[h + 2 * HN];
    float hr = g_gh[h], hz = g_gh[h + HN], hn = g_gh[h + 2 * HN];
    float r = 1.f / (1.f + expf(-(ir + hr)));
    float z = 1.f / (1.f + expf(-(iz + hz)));
    float n = tanhf(inn + r * hn);
    float hv = (1.f - z) * n + z * hid[h];
    g_hnew[h] = hv;
    out[VN + h] = hv;   // h_new output
}

// output logits: warp per row, 16 rows per 512-thread block, h_new in shared.
// Emits per-block (max, expsum) partials for split log-sum-exp.
__global__ void __launch_bounds__(512) k_logits(const float* out_W, const float* out_b) {
    __shared__ float4 h4s[HN / 4];
    __shared__ float rowv[LOGITS_ROWS];
    int t = threadIdx.x;
    h4s[t] = ((const float4*)g_hnew)[t];
    __syncthreads();
    int lane = t & 31, warp = t >> 5;
    int row = blockIdx.x * LOGITS_ROWS + warp;
    const float4* w4 = (const float4*)(out_W + (long)row * HN);
    float s = 0.f;
#pragma unroll
    for (int k = 0; k < 16; k++) {
        float4 a = w4[lane + 32 * k];
        float4 c = h4s[lane + 32 * k];
        s += a.x * c.x + a.y * c.y + a.z * c.z + a.w * c.w;
    }
    s = warpSum(s);
    if (lane == 0) {
        s += out_b[row];
        g_vlogits[row] = s;
        rowv[warp] = s;
    }
    __syncthreads();
    if (t == 0) {
        float lm = rowv[0];
#pragma unroll
        for (int i = 1; i < LOGITS_ROWS; i++) lm = fmaxf(lm, rowv[i]);
        float ls = 0.f;
#pragma unroll
        for (int i = 0; i < LOGITS_ROWS; i++) ls += expf(rowv[i] - lm);
        g_bmax[blockIdx.x] = lm;
        g_bsum[blockIdx.x] = ls;
        atomicMax(&g_maxbits, fenc(lm));   // deterministic (max order-independent)
    }
}

// finalize: every block redundantly (and deterministically) reduces the 3125
// L2-resident split-softmax partials to logZ, then writes its float4 slice.
__global__ void __launch_bounds__(256) k_finalize(float* out) {
    __shared__ float red[256];
    int t = threadIdx.x;
    float gm = fdec(g_maxbits);
    float s = 0.f;
    for (int i = t; i < NLB; i += 256) s += g_bsum[i] * expf(g_bmax[i] - gm);
    red[t] = s;
    __syncthreads();
    for (int st = 128; st; st >>= 1) {
        if (t < st) red[t] += red[t + st];
        __syncthreads();
    }
    float logZ = gm + logf(red[0]);
    int i = blockIdx.x * 256 + t;   // float4 index
    if (i < VN / 4) {
        float4 v = ((const float4*)g_vlogits)[i];
        v.x -= logZ; v.y -= logZ; v.z -= logZ; v.w -= logZ;
        ((float4*)out)[i] = v;
    }
}

extern "C" void kernel_launch(void* const* d_in, const int* in_sizes, int n_in,
                              void* d_out, int out_size) {
    const int*   tok    = (const int*)d_in[0];
    const float* hid    = (const float*)d_in[1];
    const float* enc    = (const float*)d_in[2];
    const float* emb    = (const float*)d_in[3];
    const float* attn_W = (const float*)d_in[4];
    const float* attn_b = (const float*)d_in[5];
    const float* comb_W = (const float*)d_in[6];
    const float* comb_b = (const float*)d_in[7];
    const float* W_ih   = (const float*)d_in[8];
    const float* W_hh   = (const float*)d_in[9];
    const float* b_ih   = (const float*)d_in[10];
    const float* b_hh   = (const float*)d_in[11];
    const float* out_W  = (const float*)d_in[12];
    const float* out_b  = (const float*)d_in[13];
    float* out = (float*)d_out;

    k_attnlogits_gh<<<NROWS_AG / 8, 256>>>(tok, hid, emb, attn_W, attn_b, W_hh, b_hh);
    k_attnapply<<<NCHUNK * 2, 256>>>(enc, out);
    k_attnapply_sum<<<HN / 256, 256>>>();
    k_combine<<<HN / 8, 256>>>(tok, emb, comb_W, comb_b);
    k_gru_mm<<<H3 / 8, 256>>>(W_ih, b_ih);
    k_gru_gate<<<HN / 256, 256>>>(hid, out);
    k_logits<<<NLB, 512>>>(out_W, out_b);
    k_finalize<<<(VN / 4 + 255) / 256, 256>>>(out);
}

// round 10
// speedup vs baseline: 1.0283x; 1.0283x over previous
#include <cuda_runtime.h>
#include <math.h>

#define VN 50000
#define EN 300
#define HN 2048
#define LN 512
#define EH 2348   // E + H
#define H3 6144   // 3*H
#define NROWS_AG (LN + H3)       // 6656
#define NCHUNK 32                // L-chunks for attnapply
#define LPC 16                   // L rows per chunk
#define LOGITS_ROWS 16
#define NLB (VN / LOGITS_ROWS)   // 3125 logits blocks

// ---- scratch (device globals; no allocation allowed) ----
__device__ float g_attn_logits[LN];
__device__ float g_gh[H3];
__device__ float g_gi[H3];
__device__ float g_attn_part[NCHUNK * HN];
__device__ float g_attn_applied[HN];
__device__ float g_x[HN];
__device__ float g_hnew[HN];
__device__ float g_vlogits[VN];
__device__ unsigned g_maxbits;
__device__ float g_bmax[NLB];
__device__ float g_bsum[NLB];

__device__ __forceinline__ float warpSum(float v) {
#pragma unroll
    for (int o = 16; o; o >>= 1) v += __shfl_xor_sync(0xffffffffu, v, o);
    return v;
}

// order-preserving float<->uint encoding for deterministic atomicMax
__device__ __forceinline__ unsigned fenc(float f) {
    unsigned b = __float_as_uint(f);
    return (b & 0x80000000u) ? ~b : (b | 0x80000000u);
}
__device__ __forceinline__ float fdec(unsigned u) {
    unsigned b = (u & 0x80000000u) ? (u ^ 0x80000000u) : ~u;
    return __uint_as_float(b);
}

// Dot of one 2048-float row (as float4*) against a smem-staged vector,
// with EXPLICIT 8-deep load batching: 8 independent LDG.128 are issued
// before any consumption, so MLP_eff >= 8 regardless of occupancy.
__device__ __forceinline__ float rowDot2048(const float4* __restrict__ r4,
                                            const float4* __restrict__ v4s,
                                            int lane) {
    float s = 0.f;
#pragma unroll
    for (int kb = 0; kb < 2; kb++) {
        float4 a[8];
#pragma unroll
        for (int j = 0; j < 8; j++) a[j] = r4[lane + 32 * (kb * 8 + j)];
#pragma unroll
        for (int j = 0; j < 8; j++) {
            float4 c = v4s[lane + 32 * (kb * 8 + j)];
            s += a[j].x * c.x + a[j].y * c.y + a[j].z * c.z + a[j].w * c.w;
        }
    }
    return s;
}

// Attention logits (512 rows over E+H) and gh = W_hh @ h0 + b_hh (6144 rows).
// Warp-per-row, 8 rows per 256-thread block -> 832 blocks.
__global__ void __launch_bounds__(256) k_attnlogits_gh(
        const int* tok_p, const float* hid, const float* emb,
        const float* attn_W, const float* attn_b,
        const float* W_hh, const float* b_hh) {
    __shared__ float4 h4s[HN / 4];        // h0 staged
    __shared__ float esh[EN + 4];         // emb row (only attn blocks use it)
    int t = threadIdx.x;
    if (blockIdx.x == 0 && t == 0) g_maxbits = 0u;
    h4s[t] = ((const float4*)hid)[t];
    h4s[t + 256] = ((const float4*)hid)[t + 256];
    if (blockIdx.x < LN / 8) {
        const float* e = emb + (long)(*tok_p) * EN;
        for (int i = t; i < EN; i += 256) esh[i] = e[i];
    }
    __syncthreads();
    int lane = t & 31, warp = t >> 5;
    int row = blockIdx.x * 8 + warp;
    if (row < LN) {
        const float* r = attn_W + (long)row * EH;
        float s = 0.f;
        for (int i = lane; i < EN; i += 32) s += r[i] * esh[i];
        s += rowDot2048((const float4*)(r + EN), h4s, lane);
        s = warpSum(s);
        if (lane == 0) g_attn_logits[row] = s + attn_b[row];
    } else {
        int r = row - LN;
        float s = rowDot2048((const float4*)(W_hh + (long)r * HN), h4s, lane);
        s = warpSum(s);
        if (lane == 0) g_gh[r] = s + b_hh[r];
    }
}

// Fused softmax + attn_applied partials. Every block recomputes the 512-wide
// softmax (cheap, identical across blocks), then applies its L-chunk to a
// 1024-float h-slice via float4 loads. grid = 64 blocks, 256 threads.
__global__ void k_attnapply(const float* enc, float* out) {
    __shared__ float esh[LN];
    __shared__ float red[256];
    int t = threadIdx.x;
    float v0 = g_attn_logits[t], v1 = g_attn_logits[t + 256];
    red[t] = fmaxf(v0, v1);
    __syncthreads();
    for (int s = 128; s; s >>= 1) {
        if (t < s) red[t] = fmaxf(red[t], red[t + s]);
        __syncthreads();
    }
    float m = red[0];
    __syncthreads();
    float e0 = expf(v0 - m), e1 = expf(v1 - m);
    esh[t] = e0; esh[t + 256] = e1;
    red[t] = e0 + e1;
    __syncthreads();
    for (int s = 128; s; s >>= 1) {
        if (t < s) red[t] += red[t + s];
        __syncthreads();
    }
    float inv = 1.f / red[0];

    if (blockIdx.x == 0) {  // attn_weights output
        out[VN + HN + t]       = esh[t] * inv;
        out[VN + HN + t + 256] = esh[t + 256] * inv;
    }

    int chunk = blockIdx.x >> 1, half = blockIdx.x & 1;
    int h4 = half * 256 + t;
    const float4* base = (const float4*)enc + (long)chunk * LPC * (HN / 4) + h4;
    float4 acc = make_float4(0.f, 0.f, 0.f, 0.f);
#pragma unroll
    for (int l = 0; l < LPC; l++) {
        float w = esh[chunk * LPC + l] * inv;
        float4 a = base[(long)l * (HN / 4)];
        acc.x += w * a.x; acc.y += w * a.y; acc.z += w * a.z; acc.w += w * a.w;
    }
    ((float4*)g_attn_part)[chunk * (HN / 4) + h4] = acc;
}

__global__ void k_attnapply_sum() {
    int h = blockIdx.x * 256 + threadIdx.x;
    float s = 0.f;
#pragma unroll
    for (int c = 0; c < NCHUNK; c++) s += g_attn_part[c * HN + h];
    g_attn_applied[h] = s;
}

// x = relu(comb_W @ [embedded, attn_applied] + comb_b)
// Warp-per-row, 8 rows per 256-thread block -> 256 blocks.
__global__ void __launch_bounds__(256) k_combine(const int* tok_p, const float* emb,
                                                 const float* comb_W, const float* comb_b) {
    __shared__ float4 a4s[HN / 4];
    __shared__ float esh[EN + 4];
    int t = threadIdx.x;
    a4s[t] = ((const float4*)g_attn_applied)[t];
    a4s[t + 256] = ((const float4*)g_attn_applied)[t + 256];
    {
        const float* e = emb + (long)(*tok_p) * EN;
        for (int i = t; i < EN; i += 256) esh[i] = e[i];
    }
    __syncthreads();
    int lane = t & 31, warp = t >> 5;
    int row = blockIdx.x * 8 + warp;
    const float* r = comb_W + (long)row * EH;
    float s = 0.f;
    for (int i = lane; i < EN; i += 32) s += r[i] * esh[i];
    s += rowDot2048((const float4*)(r + EN), a4s, lane);
    s = warpSum(s);
    if (lane == 0) g_x[row] = fmaxf(s + comb_b[row], 0.f);
}

// gi = W_ih @ x + b_ih : plain 6144-row GEMV, warp-per-row, 768 blocks.
__global__ void __launch_bounds__(256) k_gru_mm(const float* W_ih, const float* b_ih) {
    __shared__ float4 x4s[HN / 4];
    int t = threadIdx.x;
    x4s[t] = ((const float4*)g_x)[t];
    x4s[t + 256] = ((const float4*)g_x)[t + 256];
    __syncthreads();
    int lane = t & 31, warp = t >> 5;
    int row = blockIdx.x * 8 + warp;
    float s = rowDot2048((const float4*)(W_ih + (long)row * HN), x4s, lane);
    s = warpSum(s);
    if (lane == 0) g_gi[row] = s + b_ih[row];
}

// elementwise GRU gates -> h_new (8 blocks x 256)
__global__ void k_gru_gate(const float* hid, float* out) {
    int h = blockIdx.x * 256 + threadIdx.x;
    float ir = g_gi[h], iz = g_gi[h + HN], inn = g_gi[h + 2 * HN];
    float hr = g_gh[h], hz = g_gh[h + HN], hn = g_gh[h + 2 * HN];
    float r = 1.f / (1.f + expf(-(ir + hr)));
    float z = 1.f / (1.f + expf(-(iz + hz)));
    float n = tanhf(inn + r * hn);
    float hv = (1.f - z) * n + z * hid[h];
    g_hnew[h] = hv;
    out[VN + h] = hv;   // h_new output
}

// output logits: warp per row, 16 rows per 512-thread block, h_new in shared.
// Emits per-block (max, expsum) partials for split log-sum-exp.
__global__ void __launch_bounds__(512) k_logits(const float* out_W, const float* out_b) {
    __shared__ float4 h4s[HN / 4];
    __shared__ float rowv[LOGITS_ROWS];
    int t = threadIdx.x;
    h4s[t] = ((const float4*)g_hnew)[t];
    __syncthreads();
    int lane = t & 31, warp = t >> 5;
    int row = blockIdx.x * LOGITS_ROWS + warp;
    float s = rowDot2048((const float4*)(out_W + (long)row * HN), h4s, lane);
    s = warpSum(s);
    if (lane == 0) {
        s += out_b[row];
        g_vlogits[row] = s;
        rowv[warp] = s;
    }
    __syncthreads();
    if (t == 0) {
        float lm = rowv[0];
#pragma unroll
        for (int i = 1; i < LOGITS_ROWS; i++) lm = fmaxf(lm, rowv[i]);
        float ls = 0.f;
#pragma unroll
        for (int i = 0; i < LOGITS_ROWS; i++) ls += expf(rowv[i] - lm);
        g_bmax[blockIdx.x] = lm;
        g_bsum[blockIdx.x] = ls;
        atomicMax(&g_maxbits, fenc(lm));   // deterministic (max order-independent)
    }
}

// finalize: every block redundantly (and deterministically) reduces the 3125
// L2-resident split-softmax partials to logZ, then writes its float4 slice.
__global__ void __launch_bounds__(256) k_finalize(float* out) {
    __shared__ float red[256];
    int t = threadIdx.x;
    float gm = fdec(g_maxbits);
    float s = 0.f;
    for (int i = t; i < NLB; i += 256) s += g_bsum[i] * expf(g_bmax[i] - gm);
    red[t] = s;
    __syncthreads();
    for (int st = 128; st; st >>= 1) {
        if (t < st) red[t] += red[t + st];
        __syncthreads();
    }
    float logZ = gm + logf(red[0]);
    int i = blockIdx.x * 256 + t;   // float4 index
    if (i < VN / 4) {
        float4 v = ((const float4*)g_vlogits)[i];
        v.x -= logZ; v.y -= logZ; v.z -= logZ; v.w -= logZ;
        ((float4*)out)[i] = v;
    }
}

extern "C" void kernel_launch(void* const* d_in, const int* in_sizes, int n_in,
                              void* d_out, int out_size) {
    const int*   tok    = (const int*)d_in[0];
    const float* hid    = (const float*)d_in[1];
    const float* enc    = (const float*)d_in[2];
    const float* emb    = (const float*)d_in[3];
    const float* attn_W = (const float*)d_in[4];
    const float* attn_b = (const float*)d_in[5];
    const float* comb_W = (const float*)d_in[6];
    const float* comb_b = (const float*)d_in[7];
    const float* W_ih   = (const float*)d_in[8];
    const float* W_hh   = (const float*)d_in[9];
    const float* b_ih   = (const float*)d_in[10];
    const float* b_hh   = (const float*)d_in[11];
    const float* out_W  = (const float*)d_in[12];
    const float* out_b  = (const float*)d_in[13];
    float* out = (float*)d_out;

    k_attnlogits_gh<<<NROWS_AG / 8, 256>>>(tok, hid, emb, attn_W, attn_b, W_hh, b_hh);
    k_attnapply<<<NCHUNK * 2, 256>>>(enc, out);
    k_attnapply_sum<<<HN / 256, 256>>>();
    k_combine<<<HN / 8, 256>>>(tok, emb, comb_W, comb_b);
    k_gru_mm<<<H3 / 8, 256>>>(W_ih, b_ih);
    k_gru_gate<<<HN / 256, 256>>>(hid, out);
    k_logits<<<NLB, 512>>>(out_W, out_b);
    k_finalize<<<(VN / 4 + 255) / 256, 256>>>(out);
}

// round 15
// speedup vs baseline: 1.0644x; 1.0351x over previous
#include <cuda_runtime.h>
#include <math.h>

#define VN 50000
#define EN 300
#define HN 2048
#define LN 512
#define EH 2348   // E + H
#define H3 6144   // 3*H
#define EH4 587   // EH / 4  (EH is 16B-divisible)
#define H4 512    // HN / 4
#define E4 75     // EN / 4
#define NCHUNK 32                // L-chunks for attnapply
#define LPC 16                   // L rows per chunk
#define LOGITS_ROWS 16
#define NLB (VN / LOGITS_ROWS)   // 3125 logits blocks

// ---- scratch (device globals; no allocation allowed) ----
__device__ __align__(16) float g_attn_logits[LN];
__device__ __align__(16) float g_gh[H3];
__device__ __align__(16) float g_gi[H3];
__device__ __align__(16) float g_attn_part[NCHUNK * HN];
__device__ __align__(16) float g_cat2[EH];     // [emb row | attn_applied]
__device__ __align__(16) float g_x[HN];
__device__ __align__(16) float g_hnew[HN];
__device__ __align__(16) float g_vlogits[VN];
__device__ unsigned g_maxbits;
__device__ __align__(16) float g_bmax[NLB];
__device__ __align__(16) float g_bsum[NLB];

__device__ __forceinline__ float warpSum(float v) {
#pragma unroll
    for (int o = 16; o; o >>= 1) v += __shfl_xor_sync(0xffffffffu, v, o);
    return v;
}

// order-preserving float<->uint encoding for deterministic atomicMax
__device__ __forceinline__ unsigned fenc(float f) {
    unsigned b = __float_as_uint(f);
    return (b & 0x80000000u) ? ~b : (b | 0x80000000u);
}
__device__ __forceinline__ float fdec(unsigned u) {
    unsigned b = (u & 0x80000000u) ? (u ^ 0x80000000u) : ~u;
    return __uint_as_float(b);
}

__device__ __forceinline__ float dot4(float4 a, float4 v) {
    return a.x * v.x + a.y * v.y + a.z * v.z + a.w * v.w;
}

// ============ split-K GEMVs: 4 warps per row, 2 rows per 256-thread block ====

// Attention logits (512 rows, len 587 f4 over [emb|h0]) and
// gh = W_hh @ h0 + b_hh (6144 rows, len 512 f4). 3328 blocks.
__global__ void __launch_bounds__(256) k_attnlogits_gh(
        const int* tok_p, const float* hid, const float* emb,
        const float* attn_W, const float* attn_b,
        const float* W_hh, const float* b_hh) {
    __shared__ float part[8];
    int t = threadIdx.x, lane = t & 31, w = t >> 5;
    int rloc = w >> 2, sub = w & 3;
    int bid = blockIdx.x;
    if (bid == 0 && t == 0) g_maxbits = 0u;
    int row = bid * 2 + rloc;
    const float4* h4 = (const float4*)hid;
    float s = 0.f;
    if (row < LN) {
        const float4* r4 = (const float4*)attn_W + (long)row * EH4;
        const float4* e4 = (const float4*)emb + (long)tok_p[0] * E4;
        int i0 = sub * 147, i1 = min(i0 + 147, EH4);
        for (int i = i0 + lane; i < i1; i += 32) {
            float4 a = r4[i];
            float4 v = (i < E4) ? e4[i] : h4[i - E4];
            s += dot4(a, v);
        }
    } else {
        const float4* r4 = (const float4*)W_hh + (long)(row - LN) * H4;
        int i0 = sub * 128 + lane;
#pragma unroll
        for (int j = 0; j < 4; j++) {
            int i = i0 + 32 * j;
            s += dot4(r4[i], h4[i]);
        }
    }
    s = warpSum(s);
    if (lane == 0) part[w] = s;
    __syncthreads();
    if (t < 2) {
        int r = bid * 2 + t;
        float v = part[t * 4] + part[t * 4 + 1] + part[t * 4 + 2] + part[t * 4 + 3];
        if (r < LN) g_attn_logits[r] = v + attn_b[r];
        else        g_gh[r - LN]     = v + b_hh[r - LN];
    }
}

// Fused softmax + attn_applied partials. Every block recomputes the 512-wide
// softmax (cheap, identical across blocks), then applies its L-chunk to a
// 1024-float h-slice via float4 loads. grid = 64 blocks, 256 threads.
__global__ void k_attnapply(const float* enc, float* out) {
    __shared__ float esh[LN];
    __shared__ float red[256];
    int t = threadIdx.x;
    float v0 = g_attn_logits[t], v1 = g_attn_logits[t + 256];
    red[t] = fmaxf(v0, v1);
    __syncthreads();
    for (int s = 128; s; s >>= 1) {
        if (t < s) red[t] = fmaxf(red[t], red[t + s]);
        __syncthreads();
    }
    float m = red[0];
    __syncthreads();
    float e0 = expf(v0 - m), e1 = expf(v1 - m);
    esh[t] = e0; esh[t + 256] = e1;
    red[t] = e0 + e1;
    __syncthreads();
    for (int s = 128; s; s >>= 1) {
        if (t < s) red[t] += red[t + s];
        __syncthreads();
    }
    float inv = 1.f / red[0];

    if (blockIdx.x == 0) {  // attn_weights output
        out[VN + HN + t]       = esh[t] * inv;
        out[VN + HN + t + 256] = esh[t + 256] * inv;
    }

    int chunk = blockIdx.x >> 1, half = blockIdx.x & 1;
    int h4 = half * 256 + t;
    const float4* base = (const float4*)enc + (long)chunk * LPC * (HN / 4) + h4;
    float4 acc = make_float4(0.f, 0.f, 0.f, 0.f);
#pragma unroll
    for (int l = 0; l < LPC; l++) {
        float w = esh[chunk * LPC + l] * inv;
        float4 a = base[(long)l * (HN / 4)];
        acc.x += w * a.x; acc.y += w * a.y; acc.z += w * a.z; acc.w += w * a.w;
    }
    ((float4*)g_attn_part)[chunk * (HN / 4) + h4] = acc;
}

// reduce attn partials AND build cat2 = [emb row | attn_applied]  (8 blocks)
__global__ void k_cat2(const int* tok_p, const float* emb) {
    int h = blockIdx.x * 256 + threadIdx.x;
    float s = 0.f;
#pragma unroll
    for (int c = 0; c < NCHUNK; c++) s += g_attn_part[c * HN + h];
    g_cat2[EN + h] = s;
    if (blockIdx.x == 0) {
        const float* e = emb + (long)tok_p[0] * EN;
        for (int i = threadIdx.x; i < EN; i += 256) g_cat2[i] = e[i];
    }
}

// x = relu(comb_W @ cat2 + comb_b): 2048 rows, len 587 f4. 1024 blocks.
__global__ void __launch_bounds__(256) k_combine(const float* comb_W, const float* comb_b) {
    __shared__ float part[8];
    int t = threadIdx.x, lane = t & 31, w = t >> 5;
    int rloc = w >> 2, sub = w & 3;
    int row = blockIdx.x * 2 + rloc;
    const float4* r4 = (const float4*)comb_W + (long)row * EH4;
    const float4* c4 = (const float4*)g_cat2;
    float s = 0.f;
    int i0 = sub * 147, i1 = min(i0 + 147, EH4);
    for (int i = i0 + lane; i < i1; i += 32) s += dot4(r4[i], c4[i]);
    s = warpSum(s);
    if (lane == 0) part[w] = s;
    __syncthreads();
    if (t < 2) {
        int r = blockIdx.x * 2 + t;
        float v = part[t * 4] + part[t * 4 + 1] + part[t * 4 + 2] + part[t * 4 + 3];
        g_x[r] = fmaxf(v + comb_b[r], 0.f);
    }
}

// gi = W_ih @ x + b_ih : 6144 rows, len 512 f4. 3072 blocks.
__global__ void __launch_bounds__(256) k_gru_mm(const float* W_ih, const float* b_ih) {
    __shared__ float part[8];
    int t = threadIdx.x, lane = t & 31, w = t >> 5;
    int rloc = w >> 2, sub = w & 3;
    int row = blockIdx.x * 2 + rloc;
    const float4* r4 = (const float4*)W_ih + (long)row * H4;
    const float4* x4 = (const float4*)g_x;
    float s = 0.f;
    int i0 = sub * 128 + lane;
#pragma unroll
    for (int j = 0; j < 4; j++) {
        int i = i0 + 32 * j;
        s += dot4(r4[i], x4[i]);
    }
    s = warpSum(s);
    if (lane == 0) part[w] = s;
    __syncthreads();
    if (t < 2) {
        int r = blockIdx.x * 2 + t;
        float v = part[t * 4] + part[t * 4 + 1] + part[t * 4 + 2] + part[t * 4 + 3];
        g_gi[r] = v + b_ih[r];
    }
}

// elementwise GRU gates -> h_new (8 blocks x 256)
__global__ void k_gru_gate(const float* hid, float* out) {
    int h = blockIdx.x * 256 + threadIdx.x;
    float ir = g_gi[h], iz = g_gi[h + HN], inn = g_gi[h + 2 * HN];
    float hr = g_gh[h], hz = g_gh[h + HN], hn = g_gh[h + 2 * HN];
    float r = 1.f / (1.f + expf(-(ir + hr)));
    float z = 1.f / (1.f + expf(-(iz + hz)));
    float n = tanhf(inn + r * hn);
    float hv = (1.f - z) * n + z * hid[h];
    g_hnew[h] = hv;
    out[VN + h] = hv;   // h_new output
}

// output logits: warp per row, 16 rows per 512-thread block, h_new in shared.
// Emits per-block (max, expsum) partials for split log-sum-exp.
__global__ void __launch_bounds__(512) k_logits(const float* out_W, const float* out_b) {
    __shared__ float4 h4s[HN / 4];
    __shared__ float rowv[LOGITS_ROWS];
    int t = threadIdx.x;
    h4s[t] = ((const float4*)g_hnew)[t];
    __syncthreads();
    int lane = t & 31, warp = t >> 5;
    int row = blockIdx.x * LOGITS_ROWS + warp;
    const float4* w4 = (const float4*)(out_W + (long)row * HN);
    float s = 0.f;
#pragma unroll
    for (int k = 0; k < 16; k++) {
        float4 a = w4[lane + 32 * k];
        float4 c = h4s[lane + 32 * k];
        s += dot4(a, c);
    }
    s = warpSum(s);
    if (lane == 0) {
        s += out_b[row];
        g_vlogits[row] = s;
        rowv[warp] = s;
    }
    __syncthreads();
    if (t == 0) {
        float lm = rowv[0];
#pragma unroll
        for (int i = 1; i < LOGITS_ROWS; i++) lm = fmaxf(lm, rowv[i]);
        float ls = 0.f;
#pragma unroll
        for (int i = 0; i < LOGITS_ROWS; i++) ls += expf(rowv[i] - lm);
        g_bmax[blockIdx.x] = lm;
        g_bsum[blockIdx.x] = ls;
        atomicMax(&g_maxbits, fenc(lm));   // deterministic (max order-independent)
    }
}

// finalize: every block redundantly (and deterministically) reduces the 3125
// L2-resident split-softmax partials to logZ, then writes its float4 slice.
__global__ void __launch_bounds__(256) k_finalize(float* out) {
    __shared__ float red[256];
    int t = threadIdx.x;
    float gm = fdec(g_maxbits);
    float s = 0.f;
    for (int i = t; i < NLB; i += 256) s += g_bsum[i] * expf(g_bmax[i] - gm);
    red[t] = s;
    __syncthreads();
    for (int st = 128; st; st >>= 1) {
        if (t < st) red[t] += red[t + st];
        __syncthreads();
    }
    float logZ = gm + logf(red[0]);
    int i = blockIdx.x * 256 + t;   // float4 index
    if (i < VN / 4) {
        float4 v = ((const float4*)g_vlogits)[i];
        v.x -= logZ; v.y -= logZ; v.z -= logZ; v.w -= logZ;
        ((float4*)out)[i] = v;
    }
}

extern "C" void kernel_launch(void* const* d_in, const int* in_sizes, int n_in,
                              void* d_out, int out_size) {
    const int*   tok    = (const int*)d_in[0];
    const float* hid    = (const float*)d_in[1];
    const float* enc    = (const float*)d_in[2];
    const float* emb    = (const float*)d_in[3];
    const float* attn_W = (const float*)d_in[4];
    const float* attn_b = (const float*)d_in[5];
    const float* comb_W = (const float*)d_in[6];
    const float* comb_b = (const float*)d_in[7];
    const float* W_ih   = (const float*)d_in[8];
    const float* W_hh   = (const float*)d_in[9];
    const float* b_ih   = (const float*)d_in[10];
    const float* b_hh   = (const float*)d_in[11];
    const float* out_W  = (const float*)d_in[12];
    const float* out_b  = (const float*)d_in[13];
    float* out = (float*)d_out;

    k_attnlogits_gh<<<(LN + H3) / 2, 256>>>(tok, hid, emb, attn_W, attn_b, W_hh, b_hh);
    k_attnapply<<<NCHUNK * 2, 256>>>(enc, out);
    k_cat2<<<HN / 256, 256>>>(tok, emb);
    k_combine<<<HN / 2, 256>>>(comb_W, comb_b);
    k_gru_mm<<<H3 / 2, 256>>>(W_ih, b_ih);
    k_gru_gate<<<HN / 256, 256>>>(hid, out);
    k_logits<<<NLB, 512>>>(out_W, out_b);
    k_finalize<<<(VN / 4 + 255) / 256, 256>>>(out);
}